// round 13
// baseline (speedup 1.0000x reference)
#include <cuda_runtime.h>
#include <cuda_fp16.h>
#include <math.h>
#include <stdint.h>

#define HID 2048
#define BATCH 512
#define SEQ 128
#define NCLS 10

#define BM 64              // batch rows per CTA
#define BN 64              // hidden cols per CTA
#define KS 128             // k elements per slab
#define NSLAB (HID / KS)   // 16
#define NTHR 128           // 4 warps
#define ROW_CTAS (HID / BN)   // 32 CTAs per batch-row group

// ---- device globals (allocation-free scratch) ----
__device__ __half g_hT[2][BATCH * HID];   // hidden state, fp16, [B][K] row-major
__device__ __half g_W[HID * HID];         // whh (fp16), [N][K] row-major
__device__ unsigned g_rowbar[BATCH / BM]; // per-row step counters

// ---- SMEM layout (dynamic): 2-stage, each stage = A[2 khalves] + W[2 khalves] ----
#define SM_XS   0                 // 64 f32
#define SM_WHX  256               // 64 f32
#define SM_BH   512               // 64 f32
#define SM_SLAB 1024
#define A_OFF   0                 // [khalf][64 rows][128B]  -> 2 x 8192
#define W_OFF   16384             // [khalf][64 rows][128B]  -> 2 x 8192
#define STAGE_SZ 32768
#define SMEM_TOTAL (SM_SLAB + 2 * STAGE_SZ)   // 66560

__device__ __forceinline__ uint32_t smem_u32(const void* p) {
    uint32_t a;
    asm("{ .reg .u64 t; cvta.to.shared.u64 t, %1; cvt.u32.u64 %0, t; }" : "=r"(a) : "l"(p));
    return a;
}
__device__ __forceinline__ void cp16(uint32_t saddr, const void* g) {
    asm volatile("cp.async.cg.shared.global [%0], [%1], 16;" :: "r"(saddr), "l"(g));
}
#define CP_COMMIT() asm volatile("cp.async.commit_group;" ::: "memory")
#define CP_WAIT(n)  asm volatile("cp.async.wait_group %0;" :: "n"(n) : "memory")

#define LDSM_X4(d0, d1, d2, d3, a) \
    asm volatile("ldmatrix.sync.aligned.m8n8.x4.shared.b16 {%0,%1,%2,%3}, [%4];" \
        : "=r"(d0), "=r"(d1), "=r"(d2), "=r"(d3) : "r"(a))

#define MMA16816F16(c0, c1, c2, c3, a0, a1, a2, a3, b0, b1) \
    asm volatile("mma.sync.aligned.m16n8k16.row.col.f32.f16.f16.f32 " \
        "{%0,%1,%2,%3}, {%4,%5,%6,%7}, {%8,%9}, {%0,%1,%2,%3};" \
        : "+f"(c0), "+f"(c1), "+f"(c2), "+f"(c3) \
        : "r"(a0), "r"(a1), "r"(a2), "r"(a3), "r"(b0), "r"(b1))

// ================= one-time prep =================
__global__ __launch_bounds__(256) void convert_w(const float* __restrict__ whh) {
    int i = blockIdx.x * blockDim.x + threadIdx.x;
    if (i >= HID * HID) return;
    g_W[i] = __float2half_rn(whh[i]);
}

__global__ __launch_bounds__(256) void rnn_init(
    const float* __restrict__ whx, const float* __restrict__ bh, const float* __restrict__ x) {
    int i = blockIdx.x * blockDim.x + threadIdx.x;
    if (i < BATCH / BM) g_rowbar[i] = 0;   // reset row barriers every replay
    if (i >= BATCH * HID) return;
    int b = i / HID, m = i - b * HID;
    g_hT[0][i] = __float2half_rn(tanhf(whx[m] * x[b * SEQ + 0] + bh[m]));
}

// ================= persistent RNN: steps 1..127, per-row step barriers =================
__global__ __launch_bounds__(NTHR, 2) void rnn_persist(
    const float* __restrict__ x, const float* __restrict__ whx,
    const float* __restrict__ bh)
{
    extern __shared__ char smem[];
    uint32_t sb = smem_u32(smem);
    int tid = threadIdx.x, wid = tid >> 5, lane = tid & 31;
    int wm = wid >> 1, wn = wid & 1;      // 2x2 warps, warp tile 32m x 32n
    int n0  = blockIdx.x * BN;            // hidden col base
    int row = blockIdx.y;                 // batch-row group
    int bt0 = row * BM;                   // batch row base

    if (tid >= 64) {
        ((float*)(smem + SM_WHX))[tid - 64] = whx[n0 + tid - 64];
        ((float*)(smem + SM_BH))[tid - 64]  = bh[n0 + tid - 64];
    }

    const __half* W = g_W + (size_t)n0 * HID;

    // fragment address components (stage-independent)
    int a_row[2], w_row[2];
#pragma unroll
    for (int mt = 0; mt < 2; mt++) a_row[mt] = wm * 32 + mt * 16 + (lane & 15);
#pragma unroll
    for (int nt = 0; nt < 2; nt++) w_row[nt] = wn * 32 + nt * 16 + (lane & 7) + ((lane >> 4) << 3);
    int a_cadd = lane >> 4;          // chunk offset within k16 for A
    int w_cadd = (lane >> 3) & 1;    // chunk offset within k16 for W
    int g = lane >> 2, tg = lane & 3;

#define LOAD_SLAB(stage, ks) do {                                                \
        uint32_t sbase = sb + SM_SLAB + (stage) * STAGE_SZ;                      \
        _Pragma("unroll")                                                        \
        for (int h = 0; h < 2; h++) {                                            \
            _Pragma("unroll")                                                    \
            for (int i = 0; i < 4; i++) {                                        \
                int idx = tid + NTHR * i; int m = idx >> 3; int cc = idx & 7;    \
                uint32_t so = (uint32_t)(m * 128) + (uint32_t)((cc ^ (m & 7)) << 4); \
                size_t go = (size_t)m * HID + (ks) * KS + h * 64 + cc * 8;       \
                cp16(sbase + A_OFF + h * 8192 + so, A + go);                     \
            }                                                                    \
            _Pragma("unroll")                                                    \
            for (int i = 0; i < 4; i++) {                                        \
                int idx = tid + NTHR * i; int n = idx >> 3; int cc = idx & 7;    \
                uint32_t so = (uint32_t)(n * 128) + (uint32_t)((cc ^ (n & 7)) << 4); \
                size_t go = (size_t)n * HID + (ks) * KS + h * 64 + cc * 8;       \
                cp16(sbase + W_OFF + h * 8192 + so, W + go);                     \
            }                                                                    \
        }                                                                        \
        CP_COMMIT();                                                             \
    } while (0)

#define LD_FRAGS(bb, abase, kq) do {                                             \
        int khalf = (kq) >> 2; int cb = ((kq) & 3) * 2;                          \
        _Pragma("unroll")                                                        \
        for (int mt = 0; mt < 2; mt++) {                                         \
            int ccc = cb + a_cadd;                                               \
            uint32_t ad = (abase) + A_OFF + khalf * 8192 + a_row[mt] * 128       \
                        + ((ccc ^ (a_row[mt] & 7)) << 4);                        \
            LDSM_X4(ah[bb][mt][0], ah[bb][mt][1], ah[bb][mt][2], ah[bb][mt][3], ad); \
        }                                                                        \
        _Pragma("unroll")                                                        \
        for (int nt = 0; nt < 2; nt++) {                                         \
            int ccc = cb + w_cadd;                                               \
            uint32_t ad = (abase) + W_OFF + khalf * 8192 + w_row[nt] * 128       \
                        + ((ccc ^ (w_row[nt] & 7)) << 4);                        \
            LDSM_X4(wh[bb][nt][0], wh[bb][nt][1], wh[bb][nt][2], wh[bb][nt][3], ad); \
        }                                                                        \
    } while (0)

    uint32_t ah[2][2][4], wh[2][2][4];

#pragma unroll 1
    for (int t = 1; t < SEQ; t++) {
        int src = (t - 1) & 1, dst = t & 1;
        if (tid < 64) ((float*)(smem + SM_XS))[tid] = x[(bt0 + tid) * SEQ + t];

        const __half* A = g_hT[src] + (size_t)bt0 * HID;

        float c[2][4][4];
#pragma unroll
        for (int i = 0; i < 2; i++)
#pragma unroll
            for (int j = 0; j < 4; j++)
#pragma unroll
                for (int q = 0; q < 4; q++) c[i][j][q] = 0.f;

        LOAD_SLAB(0, 0);

#pragma unroll 1
        for (int ks = 0; ks < NSLAB; ks++) {
            if (ks + 1 < NSLAB) {
                LOAD_SLAB((ks + 1) & 1, ks + 1);
                CP_WAIT(1);
            } else {
                CP_WAIT(0);
            }
            __syncthreads();

            uint32_t abase = sb + SM_SLAB + (ks & 1) * STAGE_SZ;
            LD_FRAGS(0, abase, 0);
#pragma unroll
            for (int kq = 0; kq < 8; kq++) {
                if (kq < 7) LD_FRAGS((kq + 1) & 1, abase, kq + 1);
                int bb = kq & 1;
#pragma unroll
                for (int mt = 0; mt < 2; mt++) {
#pragma unroll
                    for (int j = 0; j < 4; j++) {
                        uint32_t b0 = wh[bb][j >> 1][(j & 1) * 2];
                        uint32_t b1 = wh[bb][j >> 1][(j & 1) * 2 + 1];
                        MMA16816F16(c[mt][j][0], c[mt][j][1], c[mt][j][2], c[mt][j][3],
                                    ah[bb][mt][0], ah[bb][mt][1], ah[bb][mt][2], ah[bb][mt][3],
                                    b0, b1);
                    }
                }
            }
            __syncthreads();
        }

        // ---- epilogue: + whx*x + bh, tanh, fp16 store ----
        {
            const float* xs   = (const float*)(smem + SM_XS);
            const float* whxs = (const float*)(smem + SM_WHX);
            const float* bhs  = (const float*)(smem + SM_BH);
            __half* D = g_hT[dst];
#pragma unroll
            for (int mt = 0; mt < 2; mt++) {
#pragma unroll
                for (int half = 0; half < 2; half++) {
                    int rloc = wm * 32 + mt * 16 + g + half * 8;
                    float xv = xs[rloc];
                    size_t rowbase = (size_t)(bt0 + rloc) * HID + n0;
#pragma unroll
                    for (int j = 0; j < 4; j++) {
                        int nloc = wn * 32 + j * 8 + 2 * tg;
                        float v0 = c[mt][j][half * 2 + 0] + whxs[nloc] * xv + bhs[nloc];
                        float v1 = c[mt][j][half * 2 + 1] + whxs[nloc + 1] * xv + bhs[nloc + 1];
                        __half2 hp = __floats2half2_rn(tanhf(v0), tanhf(v1));
                        *(__half2*)(D + rowbase + nloc) = hp;
                    }
                }
            }
        }

        // ---- per-row step barrier: only the 32 CTAs of this batch-row group ----
        if (t < SEQ - 1) {
            __syncthreads();                      // all epilogue stores issued
            if (tid == 0) {
                __threadfence();                  // release h stores to gpu scope
                atomicAdd(&g_rowbar[row], 1u);
                unsigned tgt = (unsigned)(ROW_CTAS * t);
                unsigned cur;
                do {
                    asm volatile("ld.acquire.gpu.b32 %0, [%1];" : "=r"(cur) : "l"(&g_rowbar[row]));
                } while (cur < tgt);
            }
            __syncthreads();                      // row released; also guards xs rewrite
        }
    }
#undef LOAD_SLAB
#undef LD_FRAGS
}

// ================= final projection: one warp per batch row =================
__global__ __launch_bounds__(256) void rnn_proj(
    const float* __restrict__ wph, const float* __restrict__ bp,
    float* __restrict__ out, int src)
{
    int wid = threadIdx.x >> 5, lane = threadIdx.x & 31;
    int b = blockIdx.x * 8 + wid;          // 64 blocks x 8 warps = 512 batches
    const __half2* H = (const __half2*)(g_hT[src] + (size_t)b * HID);

    float acc[NCLS];
#pragma unroll
    for (int c = 0; c < NCLS; c++) acc[c] = 0.f;

#pragma unroll 4
    for (int k2 = lane; k2 < HID / 2; k2 += 32) {
        float2 hv = __half22float2(H[k2]);
#pragma unroll
        for (int c = 0; c < NCLS; c++) {
            const float2 w = *(const float2*)(wph + c * HID + k2 * 2);
            acc[c] = fmaf(w.x, hv.x, fmaf(w.y, hv.y, acc[c]));
        }
    }
#pragma unroll
    for (int c = 0; c < NCLS; c++) {
#pragma unroll
        for (int s = 16; s > 0; s >>= 1)
            acc[c] += __shfl_xor_sync(0xFFFFFFFFu, acc[c], s);
    }
    if (lane < NCLS) out[b * NCLS + lane] = acc[lane] + bp[lane];
}

extern "C" void kernel_launch(void* const* d_in, const int* in_sizes, int n_in,
                              void* d_out, int out_size) {
    const float* x   = (const float*)d_in[0];    // [512, 128]
    const float* whx = (const float*)d_in[1];    // [2048, 1]
    const float* whh = (const float*)d_in[2];    // [2048, 2048]
    const float* bh  = (const float*)d_in[3];    // [2048, 1]
    const float* wph = (const float*)d_in[4];    // [10, 2048]
    const float* bp  = (const float*)d_in[5];    // [10, 1]
    float* out = (float*)d_out;                  // [512, 10]
    (void)in_sizes; (void)n_in; (void)out_size;

    cudaFuncSetAttribute(rnn_persist, cudaFuncAttributeMaxDynamicSharedMemorySize, SMEM_TOTAL);

    convert_w<<<(HID * HID + 255) / 256, 256>>>(whh);
    rnn_init<<<(BATCH * HID + 255) / 256, 256>>>(whx, bh, x);

    dim3 grid(HID / BN, BATCH / BM);  // (32, 8) = 256 CTAs, all co-resident (<= 296 slots)
    rnn_persist<<<grid, NTHR, SMEM_TOTAL>>>(x, whx, bh);

    rnn_proj<<<BATCH / 8, 256>>>(wph, bp, out, (SEQ - 1) & 1);  // final h in buf 1
}

// round 14
// speedup vs baseline: 1.3925x; 1.3925x over previous
#include <cuda_runtime.h>
#include <cuda_fp16.h>
#include <math.h>
#include <stdint.h>

#define HID 2048
#define BATCH 512
#define SEQ 128
#define NCLS 10

#define BM 64              // batch rows per CTA
#define BN 64              // hidden cols per CTA
#define KS 128             // k elements per slab
#define NSLAB (HID / KS)   // 16
#define NTHR 64            // 2 warps, each 32m x 64n

// ---- device globals (allocation-free scratch) ----
__device__ __half g_hT[2][BATCH * HID];   // hidden state, fp16, [B][K] row-major
__device__ __half g_W[HID * HID];         // whh (fp16), [N][K] row-major

// ---- SMEM layout (dynamic): 2-stage, each stage = A[2 khalves] + W[2 khalves] ----
#define SM_XS   0                 // 64 f32
#define SM_WHX  256               // 64 f32
#define SM_BH   512               // 64 f32
#define SM_SLAB 1024
#define A_OFF   0                 // [khalf][64 rows][128B]  -> 2 x 8192
#define W_OFF   16384             // [khalf][64 rows][128B]  -> 2 x 8192
#define STAGE_SZ 32768
#define SMEM_TOTAL (SM_SLAB + 2 * STAGE_SZ)   // 66560

__device__ __forceinline__ uint32_t smem_u32(const void* p) {
    uint32_t a;
    asm("{ .reg .u64 t; cvta.to.shared.u64 t, %1; cvt.u32.u64 %0, t; }" : "=r"(a) : "l"(p));
    return a;
}
__device__ __forceinline__ void cp16(uint32_t saddr, const void* g) {
    asm volatile("cp.async.cg.shared.global [%0], [%1], 16;" :: "r"(saddr), "l"(g));
}
#define CP_COMMIT() asm volatile("cp.async.commit_group;" ::: "memory")
#define CP_WAIT(n)  asm volatile("cp.async.wait_group %0;" :: "n"(n) : "memory")

#define LDSM_X4(d0, d1, d2, d3, a) \
    asm volatile("ldmatrix.sync.aligned.m8n8.x4.shared.b16 {%0,%1,%2,%3}, [%4];" \
        : "=r"(d0), "=r"(d1), "=r"(d2), "=r"(d3) : "r"(a))

#define MMA16816F16(c0, c1, c2, c3, a0, a1, a2, a3, b0, b1) \
    asm volatile("mma.sync.aligned.m16n8k16.row.col.f32.f16.f16.f32 " \
        "{%0,%1,%2,%3}, {%4,%5,%6,%7}, {%8,%9}, {%0,%1,%2,%3};" \
        : "+f"(c0), "+f"(c1), "+f"(c2), "+f"(c3) \
        : "r"(a0), "r"(a1), "r"(a2), "r"(a3), "r"(b0), "r"(b1))

// ================= one-time prep =================
__global__ __launch_bounds__(256) void convert_w(const float* __restrict__ whh) {
    int i = blockIdx.x * blockDim.x + threadIdx.x;
    if (i >= HID * HID) return;
    g_W[i] = __float2half_rn(whh[i]);
}

__global__ __launch_bounds__(256) void rnn_init(
    const float* __restrict__ whx, const float* __restrict__ bh, const float* __restrict__ x) {
    int i = blockIdx.x * blockDim.x + threadIdx.x;
    if (i >= BATCH * HID) return;
    int b = i / HID, m = i - b * HID;
    g_hT[0][i] = __float2half_rn(tanhf(whx[m] * x[b * SEQ + 0] + bh[m]));
}

// ================= per-step GEMM: hT_new = tanh(hT @ W^T + whx*x_t + bh) =================
__global__ __launch_bounds__(NTHR, 2) void rnn_step_mma(
    const float* __restrict__ x, const float* __restrict__ whx,
    const float* __restrict__ bh, int t, int src, int dst)
{
    extern __shared__ char smem[];
    uint32_t sb = smem_u32(smem);
    int tid = threadIdx.x, wid = tid >> 5, lane = tid & 31;
    int wm = wid;                         // 2 warps: warp tile 32m x 64n
    int n0  = blockIdx.x * BN;            // hidden col base
    int bt0 = blockIdx.y * BM;            // batch row base

    ((float*)(smem + SM_XS))[tid]  = x[(bt0 + tid) * SEQ + t];
    ((float*)(smem + SM_WHX))[tid] = whx[n0 + tid];
    ((float*)(smem + SM_BH))[tid]  = bh[n0 + tid];

    const __half* A = g_hT[src] + (size_t)bt0 * HID;
    const __half* W = g_W + (size_t)n0 * HID;

    float c[2][8][4];   // mt x n8-group x quad
#pragma unroll
    for (int i = 0; i < 2; i++)
#pragma unroll
        for (int j = 0; j < 8; j++)
#pragma unroll
            for (int q = 0; q < 4; q++) c[i][j][q] = 0.f;

    // fragment address components (stage-independent)
    int a_row[2], w_row[4];
#pragma unroll
    for (int mt = 0; mt < 2; mt++) a_row[mt] = wm * 32 + mt * 16 + (lane & 15);
#pragma unroll
    for (int nt = 0; nt < 4; nt++) w_row[nt] = nt * 16 + (lane & 7) + ((lane >> 4) << 3);
    int a_cadd = lane >> 4;          // chunk offset within k16 for A
    int w_cadd = (lane >> 3) & 1;    // chunk offset within k16 for W
    int g = lane >> 2, tg = lane & 3;

#define LOAD_SLAB(stage, ks) do {                                                \
        uint32_t sbase = sb + SM_SLAB + (stage) * STAGE_SZ;                      \
        _Pragma("unroll")                                                        \
        for (int h = 0; h < 2; h++) {                                            \
            _Pragma("unroll")                                                    \
            for (int i = 0; i < 8; i++) {                                        \
                int idx = tid + NTHR * i; int m = idx >> 3; int cc = idx & 7;    \
                uint32_t so = (uint32_t)(m * 128) + (uint32_t)((cc ^ (m & 7)) << 4); \
                size_t go = (size_t)m * HID + (ks) * KS + h * 64 + cc * 8;       \
                cp16(sbase + A_OFF + h * 8192 + so, A + go);                     \
            }                                                                    \
            _Pragma("unroll")                                                    \
            for (int i = 0; i < 8; i++) {                                        \
                int idx = tid + NTHR * i; int n = idx >> 3; int cc = idx & 7;    \
                uint32_t so = (uint32_t)(n * 128) + (uint32_t)((cc ^ (n & 7)) << 4); \
                size_t go = (size_t)n * HID + (ks) * KS + h * 64 + cc * 8;       \
                cp16(sbase + W_OFF + h * 8192 + so, W + go);                     \
            }                                                                    \
        }                                                                        \
        CP_COMMIT();                                                             \
    } while (0)

// load ldmatrix fragments for k16-iter kq (0..7) of the slab at abase into buffer bb
#define LD_FRAGS(bb, abase, kq) do {                                             \
        int khalf = (kq) >> 2; int cb = ((kq) & 3) * 2;                          \
        _Pragma("unroll")                                                        \
        for (int mt = 0; mt < 2; mt++) {                                         \
            int ccc = cb + a_cadd;                                               \
            uint32_t ad = (abase) + A_OFF + khalf * 8192 + a_row[mt] * 128       \
                        + ((ccc ^ (a_row[mt] & 7)) << 4);                        \
            LDSM_X4(ah[bb][mt][0], ah[bb][mt][1], ah[bb][mt][2], ah[bb][mt][3], ad); \
        }                                                                        \
        _Pragma("unroll")                                                        \
        for (int nt = 0; nt < 4; nt++) {                                         \
            int ccc = cb + w_cadd;                                               \
            uint32_t ad = (abase) + W_OFF + khalf * 8192 + w_row[nt] * 128       \
                        + ((ccc ^ (w_row[nt] & 7)) << 4);                        \
            LDSM_X4(wh[bb][nt][0], wh[bb][nt][1], wh[bb][nt][2], wh[bb][nt][3], ad); \
        }                                                                        \
    } while (0)

    LOAD_SLAB(0, 0);

    uint32_t ah[2][2][4], wh[2][4][4];

#pragma unroll 1
    for (int ks = 0; ks < NSLAB; ks++) {
        if (ks + 1 < NSLAB) {
            LOAD_SLAB((ks + 1) & 1, ks + 1);
            CP_WAIT(1);
        } else {
            CP_WAIT(0);
        }
        __syncthreads();

        uint32_t abase = sb + SM_SLAB + (ks & 1) * STAGE_SZ;
        LD_FRAGS(0, abase, 0);
#pragma unroll
        for (int kq = 0; kq < 8; kq++) {
            if (kq < 7) LD_FRAGS((kq + 1) & 1, abase, kq + 1);
            int bb = kq & 1;
#pragma unroll
            for (int mt = 0; mt < 2; mt++) {
#pragma unroll
                for (int j = 0; j < 8; j++) {
                    uint32_t b0 = wh[bb][j >> 1][(j & 1) * 2];
                    uint32_t b1 = wh[bb][j >> 1][(j & 1) * 2 + 1];
                    MMA16816F16(c[mt][j][0], c[mt][j][1], c[mt][j][2], c[mt][j][3],
                                ah[bb][mt][0], ah[bb][mt][1], ah[bb][mt][2], ah[bb][mt][3],
                                b0, b1);
                }
            }
        }
        __syncthreads();
    }
#undef LOAD_SLAB
#undef LD_FRAGS

    // ---- epilogue: + whx*x + bh, tanh, fp16 store ----
    const float* xs   = (const float*)(smem + SM_XS);
    const float* whxs = (const float*)(smem + SM_WHX);
    const float* bhs  = (const float*)(smem + SM_BH);
    __half* D = g_hT[dst];

#pragma unroll
    for (int mt = 0; mt < 2; mt++) {
#pragma unroll
        for (int half = 0; half < 2; half++) {
            int rloc = wm * 32 + mt * 16 + g + half * 8;
            float xv = xs[rloc];
            size_t rowbase = (size_t)(bt0 + rloc) * HID + n0;
#pragma unroll
            for (int j = 0; j < 8; j++) {
                int nloc = j * 8 + 2 * tg;
                float v0 = c[mt][j][half * 2 + 0] + whxs[nloc] * xv + bhs[nloc];
                float v1 = c[mt][j][half * 2 + 1] + whxs[nloc + 1] * xv + bhs[nloc + 1];
                __half2 hp = __floats2half2_rn(tanhf(v0), tanhf(v1));
                *(__half2*)(D + rowbase + nloc) = hp;
            }
        }
    }
}

// ================= final projection: one warp per batch row =================
__global__ __launch_bounds__(256) void rnn_proj(
    const float* __restrict__ wph, const float* __restrict__ bp,
    float* __restrict__ out, int src)
{
    int wid = threadIdx.x >> 5, lane = threadIdx.x & 31;
    int b = blockIdx.x * 8 + wid;          // 64 blocks x 8 warps = 512 batches
    const __half2* H = (const __half2*)(g_hT[src] + (size_t)b * HID);

    float acc[NCLS];
#pragma unroll
    for (int c = 0; c < NCLS; c++) acc[c] = 0.f;

#pragma unroll 4
    for (int k2 = lane; k2 < HID / 2; k2 += 32) {
        float2 hv = __half22float2(H[k2]);
#pragma unroll
        for (int c = 0; c < NCLS; c++) {
            const float2 w = *(const float2*)(wph + c * HID + k2 * 2);
            acc[c] = fmaf(w.x, hv.x, fmaf(w.y, hv.y, acc[c]));
        }
    }
#pragma unroll
    for (int c = 0; c < NCLS; c++) {
#pragma unroll
        for (int s = 16; s > 0; s >>= 1)
            acc[c] += __shfl_xor_sync(0xFFFFFFFFu, acc[c], s);
    }
    if (lane < NCLS) out[b * NCLS + lane] = acc[lane] + bp[lane];
}

extern "C" void kernel_launch(void* const* d_in, const int* in_sizes, int n_in,
                              void* d_out, int out_size) {
    const float* x   = (const float*)d_in[0];    // [512, 128]
    const float* whx = (const float*)d_in[1];    // [2048, 1]
    const float* whh = (const float*)d_in[2];    // [2048, 2048]
    const float* bh  = (const float*)d_in[3];    // [2048, 1]
    const float* wph = (const float*)d_in[4];    // [10, 2048]
    const float* bp  = (const float*)d_in[5];    // [10, 1]
    float* out = (float*)d_out;                  // [512, 10]
    (void)in_sizes; (void)n_in; (void)out_size;

    cudaFuncSetAttribute(rnn_step_mma, cudaFuncAttributeMaxDynamicSharedMemorySize, SMEM_TOTAL);

    convert_w<<<(HID * HID + 255) / 256, 256>>>(whh);
    rnn_init<<<(BATCH * HID + 255) / 256, 256>>>(whx, bh, x);

    dim3 grid(HID / BN, BATCH / BM);  // (32, 8) = 256 CTAs -> 2 CTAs/SM
    for (int t = 1; t < SEQ; t++) {
        rnn_step_mma<<<grid, NTHR, SMEM_TOTAL>>>(x, whx, bh, t, (t - 1) & 1, t & 1);
    }

    rnn_proj<<<BATCH / 8, 256>>>(wph, bp, out, (SEQ - 1) & 1);  // final h in buf 1
}

// round 15
// speedup vs baseline: 1.5292x; 1.0982x over previous
#include <cuda_runtime.h>
#include <cuda_fp16.h>
#include <math.h>
#include <stdint.h>

#define HID 2048
#define BATCH 512
#define SEQ 128
#define NCLS 10

#define BM 64              // batch rows per CTA
#define BN 64              // hidden cols per CTA
#define KS 128             // k elements per slab
#define NSLAB (HID / KS)   // 16
#define NTHR 128           // 4 warps

// ---- device globals (allocation-free scratch) ----
__device__ __half g_hT[2][BATCH * HID];   // hidden state, fp16, [B][K] row-major
__device__ __half g_W[HID * HID];         // whh (fp16), [N][K] row-major

// ---- SMEM layout (dynamic): 2-stage, each stage = A[2 khalves] + W[2 khalves] ----
#define SM_XS   0                 // 64 f32
#define SM_WHX  256               // 64 f32
#define SM_BH   512               // 64 f32
#define SM_SLAB 1024
#define A_OFF   0                 // [khalf][64 rows][128B]  -> 2 x 8192
#define W_OFF   16384             // [khalf][64 rows][128B]  -> 2 x 8192
#define STAGE_SZ 32768
#define SMEM_TOTAL (SM_SLAB + 2 * STAGE_SZ)   // 66560

__device__ __forceinline__ uint32_t smem_u32(const void* p) {
    uint32_t a;
    asm("{ .reg .u64 t; cvta.to.shared.u64 t, %1; cvt.u32.u64 %0, t; }" : "=r"(a) : "l"(p));
    return a;
}
__device__ __forceinline__ void cp16(uint32_t saddr, const void* g) {
    asm volatile("cp.async.cg.shared.global [%0], [%1], 16;" :: "r"(saddr), "l"(g));
}
#define CP_COMMIT() asm volatile("cp.async.commit_group;" ::: "memory")
#define CP_WAIT(n)  asm volatile("cp.async.wait_group %0;" :: "n"(n) : "memory")

#define LDSM_X4(d0, d1, d2, d3, a) \
    asm volatile("ldmatrix.sync.aligned.m8n8.x4.shared.b16 {%0,%1,%2,%3}, [%4];" \
        : "=r"(d0), "=r"(d1), "=r"(d2), "=r"(d3) : "r"(a))

#define MMA16816F16(c0, c1, c2, c3, a0, a1, a2, a3, b0, b1) \
    asm volatile("mma.sync.aligned.m16n8k16.row.col.f32.f16.f16.f32 " \
        "{%0,%1,%2,%3}, {%4,%5,%6,%7}, {%8,%9}, {%0,%1,%2,%3};" \
        : "+f"(c0), "+f"(c1), "+f"(c2), "+f"(c3) \
        : "r"(a0), "r"(a1), "r"(a2), "r"(a3), "r"(b0), "r"(b1))

// ================= one-time prep =================
__global__ __launch_bounds__(256) void convert_w(const float* __restrict__ whh) {
    int i = blockIdx.x * blockDim.x + threadIdx.x;
    if (i >= HID * HID) return;
    g_W[i] = __float2half_rn(whh[i]);
}

__global__ __launch_bounds__(256) void rnn_init(
    const float* __restrict__ whx, const float* __restrict__ bh, const float* __restrict__ x) {
    int i = blockIdx.x * blockDim.x + threadIdx.x;
    if (i >= BATCH * HID) return;
    int b = i / HID, m = i - b * HID;
    g_hT[0][i] = __float2half_rn(tanhf(whx[m] * x[b * SEQ + 0] + bh[m]));
}

// ================= per-step GEMM: hT_new = tanh(hT @ W^T + whx*x_t + bh) =================
__global__ __launch_bounds__(NTHR, 2) void rnn_step_mma(
    const float* __restrict__ x, const float* __restrict__ whx,
    const float* __restrict__ bh, int t, int src, int dst)
{
    extern __shared__ char smem[];
    uint32_t sb = smem_u32(smem);
    int tid = threadIdx.x, wid = tid >> 5, lane = tid & 31;
    int wm = wid >> 1, wn = wid & 1;      // 2x2 warps, warp tile 32m x 32n
    int n0  = blockIdx.x * BN;            // hidden col base
    int bt0 = blockIdx.y * BM;            // batch row base

    if (tid < 64) {
        ((float*)(smem + SM_XS))[tid] = x[(bt0 + tid) * SEQ + t];
    } else {
        ((float*)(smem + SM_WHX))[tid - 64] = whx[n0 + tid - 64];
        ((float*)(smem + SM_BH))[tid - 64]  = bh[n0 + tid - 64];
    }

    const __half* A = g_hT[src] + (size_t)bt0 * HID;
    const __half* W = g_W + (size_t)n0 * HID;

    float c[2][4][4], c2[2][4][4];   // dual accumulator banks (even/odd kq)
#pragma unroll
    for (int i = 0; i < 2; i++)
#pragma unroll
        for (int j = 0; j < 4; j++)
#pragma unroll
            for (int q = 0; q < 4; q++) { c[i][j][q] = 0.f; c2[i][j][q] = 0.f; }

    // fragment address components (stage-independent)
    int a_row[2], w_row[2];
#pragma unroll
    for (int mt = 0; mt < 2; mt++) a_row[mt] = wm * 32 + mt * 16 + (lane & 15);
#pragma unroll
    for (int nt = 0; nt < 2; nt++) w_row[nt] = wn * 32 + nt * 16 + (lane & 7) + ((lane >> 4) << 3);
    int a_cadd = lane >> 4;          // chunk offset within k16 for A
    int w_cadd = (lane >> 3) & 1;    // chunk offset within k16 for W
    int g = lane >> 2, tg = lane & 3;

    // per-thread load-mapping components (each chunk = 128 threads x 16B = 2KB)
    int ld_m = tid >> 3;             // row 0..15 within a chunk's 16-row span? no: see below
    int ld_cc = tid & 7;
    // chunk ch (0..7) of A: h = ch>>2 (khalf), i = ch&3 -> rows [i*16 .. i*16+15]
    // row = (tid + 128*i) >> 3 = tid>>3 + 16*i ; cc = tid & 7

#define LOAD_CHUNK_A(sbase, ks, ch) do {                                         \
        int h_ = (ch) >> 2, i_ = (ch) & 3;                                       \
        int m_ = ld_m + 16 * i_;                                                 \
        uint32_t so = (uint32_t)(m_ * 128) + (uint32_t)((ld_cc ^ (m_ & 7)) << 4); \
        size_t go = (size_t)m_ * HID + (ks) * KS + h_ * 64 + ld_cc * 8;          \
        cp16((sbase) + A_OFF + h_ * 8192 + so, A + go);                          \
    } while (0)

#define LOAD_CHUNK_W(sbase, ks, ch) do {                                         \
        int h_ = (ch) >> 2, i_ = (ch) & 3;                                       \
        int n_ = ld_m + 16 * i_;                                                 \
        uint32_t so = (uint32_t)(n_ * 128) + (uint32_t)((ld_cc ^ (n_ & 7)) << 4); \
        size_t go = (size_t)n_ * HID + (ks) * KS + h_ * 64 + ld_cc * 8;          \
        cp16((sbase) + W_OFF + h_ * 8192 + so, W + go);                          \
    } while (0)

// load ldmatrix fragments for k16-iter kq (0..7) of the slab at abase into buffer bb
#define LD_FRAGS(bb, abase, kq) do {                                             \
        int khalf = (kq) >> 2; int cb = ((kq) & 3) * 2;                          \
        _Pragma("unroll")                                                        \
        for (int mt = 0; mt < 2; mt++) {                                         \
            int ccc = cb + a_cadd;                                               \
            uint32_t ad = (abase) + A_OFF + khalf * 8192 + a_row[mt] * 128       \
                        + ((ccc ^ (a_row[mt] & 7)) << 4);                        \
            LDSM_X4(ah[bb][mt][0], ah[bb][mt][1], ah[bb][mt][2], ah[bb][mt][3], ad); \
        }                                                                        \
        _Pragma("unroll")                                                        \
        for (int nt = 0; nt < 2; nt++) {                                         \
            int ccc = cb + w_cadd;                                               \
            uint32_t ad = (abase) + W_OFF + khalf * 8192 + w_row[nt] * 128       \
                        + ((ccc ^ (w_row[nt] & 7)) << 4);                        \
            LDSM_X4(wh[bb][nt][0], wh[bb][nt][1], wh[bb][nt][2], wh[bb][nt][3], ad); \
        }                                                                        \
    } while (0)

    // prologue: slab 0 as one group
    {
        uint32_t sbase0 = sb + SM_SLAB;
#pragma unroll
        for (int ch = 0; ch < 8; ch++) { LOAD_CHUNK_A(sbase0, 0, ch); LOAD_CHUNK_W(sbase0, 0, ch); }
        CP_COMMIT();
    }

    uint32_t ah[2][2][4], wh[2][2][4];

#pragma unroll 1
    for (int ks = 0; ks < NSLAB; ks++) {
        CP_WAIT(0);          // current slab's group (committed last iteration) is complete
        __syncthreads();     // also proves prior-slab reads finished before overwrite

        uint32_t abase = sb + SM_SLAB + (ks & 1) * STAGE_SZ;
        uint32_t nbase = sb + SM_SLAB + ((ks + 1) & 1) * STAGE_SZ;
        int have_next = (ks + 1 < NSLAB);

        LD_FRAGS(0, abase, 0);
#pragma unroll
        for (int kq = 0; kq < 8; kq++) {
            // staggered next-slab loads: 4 chunks per kq for kq = 0..3
            if (kq < 4 && have_next) {
                LOAD_CHUNK_A(nbase, ks + 1, 2 * kq);
                LOAD_CHUNK_A(nbase, ks + 1, 2 * kq + 1);
                LOAD_CHUNK_W(nbase, ks + 1, 2 * kq);
                LOAD_CHUNK_W(nbase, ks + 1, 2 * kq + 1);
                if (kq == 3) CP_COMMIT();
            }
            if (kq < 7) LD_FRAGS((kq + 1) & 1, abase, kq + 1);
            int bb = kq & 1;
#pragma unroll
            for (int mt = 0; mt < 2; mt++) {
#pragma unroll
                for (int j = 0; j < 4; j++) {
                    uint32_t b0 = wh[bb][j >> 1][(j & 1) * 2];
                    uint32_t b1 = wh[bb][j >> 1][(j & 1) * 2 + 1];
                    if (kq & 1) {
                        MMA16816F16(c2[mt][j][0], c2[mt][j][1], c2[mt][j][2], c2[mt][j][3],
                                    ah[bb][mt][0], ah[bb][mt][1], ah[bb][mt][2], ah[bb][mt][3],
                                    b0, b1);
                    } else {
                        MMA16816F16(c[mt][j][0], c[mt][j][1], c[mt][j][2], c[mt][j][3],
                                    ah[bb][mt][0], ah[bb][mt][1], ah[bb][mt][2], ah[bb][mt][3],
                                    b0, b1);
                    }
                }
            }
        }
        __syncthreads();
    }
#undef LOAD_CHUNK_A
#undef LOAD_CHUNK_W
#undef LD_FRAGS

    // ---- epilogue: merge banks, + whx*x + bh, tanh, fp16 store ----
    const float* xs   = (const float*)(smem + SM_XS);
    const float* whxs = (const float*)(smem + SM_WHX);
    const float* bhs  = (const float*)(smem + SM_BH);
    __half* D = g_hT[dst];

#pragma unroll
    for (int mt = 0; mt < 2; mt++) {
#pragma unroll
        for (int half = 0; half < 2; half++) {
            int rloc = wm * 32 + mt * 16 + g + half * 8;
            float xv = xs[rloc];
            size_t rowbase = (size_t)(bt0 + rloc) * HID + n0;
#pragma unroll
            for (int j = 0; j < 4; j++) {
                int nloc = wn * 32 + j * 8 + 2 * tg;
                float v0 = c[mt][j][half * 2 + 0] + c2[mt][j][half * 2 + 0]
                         + whxs[nloc] * xv + bhs[nloc];
                float v1 = c[mt][j][half * 2 + 1] + c2[mt][j][half * 2 + 1]
                         + whxs[nloc + 1] * xv + bhs[nloc + 1];
                __half2 hp = __floats2half2_rn(tanhf(v0), tanhf(v1));
                *(__half2*)(D + rowbase + nloc) = hp;
            }
        }
    }
}

// ================= final projection: one warp per batch row =================
__global__ __launch_bounds__(256) void rnn_proj(
    const float* __restrict__ wph, const float* __restrict__ bp,
    float* __restrict__ out, int src)
{
    int wid = threadIdx.x >> 5, lane = threadIdx.x & 31;
    int b = blockIdx.x * 8 + wid;          // 64 blocks x 8 warps = 512 batches
    const __half2* H = (const __half2*)(g_hT[src] + (size_t)b * HID);

    float acc[NCLS];
#pragma unroll
    for (int c = 0; c < NCLS; c++) acc[c] = 0.f;

#pragma unroll 4
    for (int k2 = lane; k2 < HID / 2; k2 += 32) {
        float2 hv = __half22float2(H[k2]);
#pragma unroll
        for (int c = 0; c < NCLS; c++) {
            const float2 w = *(const float2*)(wph + c * HID + k2 * 2);
            acc[c] = fmaf(w.x, hv.x, fmaf(w.y, hv.y, acc[c]));
        }
    }
#pragma unroll
    for (int c = 0; c < NCLS; c++) {
#pragma unroll
        for (int s = 16; s > 0; s >>= 1)
            acc[c] += __shfl_xor_sync(0xFFFFFFFFu, acc[c], s);
    }
    if (lane < NCLS) out[b * NCLS + lane] = acc[lane] + bp[lane];
}

extern "C" void kernel_launch(void* const* d_in, const int* in_sizes, int n_in,
                              void* d_out, int out_size) {
    const float* x   = (const float*)d_in[0];    // [512, 128]
    const float* whx = (const float*)d_in[1];    // [2048, 1]
    const float* whh = (const float*)d_in[2];    // [2048, 2048]
    const float* bh  = (const float*)d_in[3];    // [2048, 1]
    const float* wph = (const float*)d_in[4];    // [10, 2048]
    const float* bp  = (const float*)d_in[5];    // [10, 1]
    float* out = (float*)d_out;                  // [512, 10]
    (void)in_sizes; (void)n_in; (void)out_size;

    cudaFuncSetAttribute(rnn_step_mma, cudaFuncAttributeMaxDynamicSharedMemorySize, SMEM_TOTAL);

    convert_w<<<(HID * HID + 255) / 256, 256>>>(whh);
    rnn_init<<<(BATCH * HID + 255) / 256, 256>>>(whx, bh, x);

    dim3 grid(HID / BN, BATCH / BM);  // (32, 8) = 256 CTAs -> 2 CTAs/SM
    for (int t = 1; t < SEQ; t++) {
        rnn_step_mma<<<grid, NTHR, SMEM_TOTAL>>>(x, whx, bh, t, (t - 1) & 1, t & 1);
    }

    rnn_proj<<<BATCH / 8, 256>>>(wph, bp, out, (SEQ - 1) & 1);  // final h in buf 1
}

// round 16
// speedup vs baseline: 1.5986x; 1.0454x over previous
#include <cuda_runtime.h>
#include <cuda_fp16.h>
#include <math.h>
#include <stdint.h>

#define HID 2048
#define BATCH 512
#define SEQ 128
#define NCLS 10

#define BM 64              // batch rows per CTA
#define BN 64              // hidden cols per CTA
#define KS 128             // k elements per slab
#define NSLAB (HID / KS)   // 16
#define NTHR 128           // 4 warps

// ---- device globals (allocation-free scratch) ----
__device__ __half g_hT[2][BATCH * HID];   // hidden state, fp16, [B][K] row-major
__device__ __half g_W[HID * HID];         // whh (fp16), [N][K] row-major

// ---- SMEM layout (dynamic): 2-stage, each stage = A[2 khalves] + W[2 khalves] ----
#define SM_XS   0                 // 64 f32
#define SM_WHX  256               // 64 f32
#define SM_BH   512               // 64 f32
#define SM_SLAB 1024
#define A_OFF   0                 // [khalf][64 rows][128B]  -> 2 x 8192
#define W_OFF   16384             // [khalf][64 rows][128B]  -> 2 x 8192
#define STAGE_SZ 32768
#define SMEM_TOTAL (SM_SLAB + 2 * STAGE_SZ)   // 66560

__device__ __forceinline__ uint32_t smem_u32(const void* p) {
    uint32_t a;
    asm("{ .reg .u64 t; cvta.to.shared.u64 t, %1; cvt.u32.u64 %0, t; }" : "=r"(a) : "l"(p));
    return a;
}
__device__ __forceinline__ void cp16(uint32_t saddr, const void* g) {
    asm volatile("cp.async.cg.shared.global [%0], [%1], 16;" :: "r"(saddr), "l"(g));
}
#define CP_COMMIT() asm volatile("cp.async.commit_group;" ::: "memory")
#define CP_WAIT(n)  asm volatile("cp.async.wait_group %0;" :: "n"(n) : "memory")

#define LDSM_X4(d0, d1, d2, d3, a) \
    asm volatile("ldmatrix.sync.aligned.m8n8.x4.shared.b16 {%0,%1,%2,%3}, [%4];" \
        : "=r"(d0), "=r"(d1), "=r"(d2), "=r"(d3) : "r"(a))

#define MMA16816F16(c0, c1, c2, c3, a0, a1, a2, a3, b0, b1) \
    asm volatile("mma.sync.aligned.m16n8k16.row.col.f32.f16.f16.f32 " \
        "{%0,%1,%2,%3}, {%4,%5,%6,%7}, {%8,%9}, {%0,%1,%2,%3};" \
        : "+f"(c0), "+f"(c1), "+f"(c2), "+f"(c3) \
        : "r"(a0), "r"(a1), "r"(a2), "r"(a3), "r"(b0), "r"(b1))

// ================= one-time prep =================
__global__ __launch_bounds__(256) void convert_w(const float* __restrict__ whh) {
    int i = blockIdx.x * blockDim.x + threadIdx.x;
    if (i >= HID * HID) return;
    g_W[i] = __float2half_rn(whh[i]);
}

__global__ __launch_bounds__(256) void rnn_init(
    const float* __restrict__ whx, const float* __restrict__ bh, const float* __restrict__ x) {
    int i = blockIdx.x * blockDim.x + threadIdx.x;
    if (i >= BATCH * HID) return;
    int b = i / HID, m = i - b * HID;
    g_hT[0][i] = __float2half_rn(tanhf(whx[m] * x[b * SEQ + 0] + bh[m]));
}

// ================= per-step GEMM: hT_new = tanh(hT @ W^T + whx*x_t + bh) =================
__global__ __launch_bounds__(NTHR, 2) void rnn_step_mma(
    const float* __restrict__ x, const float* __restrict__ whx,
    const float* __restrict__ bh, int t, int src, int dst)
{
    extern __shared__ char smem[];
    uint32_t sb = smem_u32(smem);
    int tid = threadIdx.x, wid = tid >> 5, lane = tid & 31;
    int wm = wid >> 1, wn = wid & 1;      // 2x2 warps, warp tile 32m x 32n
    int n0  = blockIdx.x * BN;            // hidden col base
    int bt0 = blockIdx.y * BM;            // batch row base

    // ===== PDL pre-sync region: touch ONLY static inputs (x, whx, bh, g_W) =====
    if (tid < 64) {
        ((float*)(smem + SM_XS))[tid] = x[(bt0 + tid) * SEQ + t];
    } else {
        ((float*)(smem + SM_WHX))[tid - 64] = whx[n0 + tid - 64];
        ((float*)(smem + SM_BH))[tid - 64]  = bh[n0 + tid - 64];
    }

    const __half* A = g_hT[src] + (size_t)bt0 * HID;
    const __half* W = g_W + (size_t)n0 * HID;

    float c[2][4][4], c2[2][4][4];   // dual accumulator banks (even/odd kq)
#pragma unroll
    for (int i = 0; i < 2; i++)
#pragma unroll
        for (int j = 0; j < 4; j++)
#pragma unroll
            for (int q = 0; q < 4; q++) { c[i][j][q] = 0.f; c2[i][j][q] = 0.f; }

    // fragment address components (stage-independent)
    int a_row[2], w_row[2];
#pragma unroll
    for (int mt = 0; mt < 2; mt++) a_row[mt] = wm * 32 + mt * 16 + (lane & 15);
#pragma unroll
    for (int nt = 0; nt < 2; nt++) w_row[nt] = wn * 32 + nt * 16 + (lane & 7) + ((lane >> 4) << 3);
    int a_cadd = lane >> 4;          // chunk offset within k16 for A
    int w_cadd = (lane >> 3) & 1;    // chunk offset within k16 for W
    int g = lane >> 2, tg = lane & 3;

    // per-thread load-mapping components (each chunk = 128 threads x 16B = 2KB)
    int ld_m = tid >> 3;
    int ld_cc = tid & 7;

#define LOAD_CHUNK_A(sbase, ks, ch) do {                                         \
        int h_ = (ch) >> 2, i_ = (ch) & 3;                                       \
        int m_ = ld_m + 16 * i_;                                                 \
        uint32_t so = (uint32_t)(m_ * 128) + (uint32_t)((ld_cc ^ (m_ & 7)) << 4); \
        size_t go = (size_t)m_ * HID + (ks) * KS + h_ * 64 + ld_cc * 8;          \
        cp16((sbase) + A_OFF + h_ * 8192 + so, A + go);                          \
    } while (0)

#define LOAD_CHUNK_W(sbase, ks, ch) do {                                         \
        int h_ = (ch) >> 2, i_ = (ch) & 3;                                       \
        int n_ = ld_m + 16 * i_;                                                 \
        uint32_t so = (uint32_t)(n_ * 128) + (uint32_t)((ld_cc ^ (n_ & 7)) << 4); \
        size_t go = (size_t)n_ * HID + (ks) * KS + h_ * 64 + ld_cc * 8;          \
        cp16((sbase) + W_OFF + h_ * 8192 + so, W + go);                          \
    } while (0)

#define LD_FRAGS(bb, abase, kq) do {                                             \
        int khalf = (kq) >> 2; int cb = ((kq) & 3) * 2;                          \
        _Pragma("unroll")                                                        \
        for (int mt = 0; mt < 2; mt++) {                                         \
            int ccc = cb + a_cadd;                                               \
            uint32_t ad = (abase) + A_OFF + khalf * 8192 + a_row[mt] * 128       \
                        + ((ccc ^ (a_row[mt] & 7)) << 4);                        \
            LDSM_X4(ah[bb][mt][0], ah[bb][mt][1], ah[bb][mt][2], ah[bb][mt][3], ad); \
        }                                                                        \
        _Pragma("unroll")                                                        \
        for (int nt = 0; nt < 2; nt++) {                                         \
            int ccc = cb + w_cadd;                                               \
            uint32_t ad = (abase) + W_OFF + khalf * 8192 + w_row[nt] * 128       \
                        + ((ccc ^ (w_row[nt] & 7)) << 4);                        \
            LDSM_X4(wh[bb][nt][0], wh[bb][nt][1], wh[bb][nt][2], wh[bb][nt][3], ad); \
        }                                                                        \
    } while (0)

    // W half of slab 0: static data, issue before the grid dependency resolves
    {
        uint32_t sbase0 = sb + SM_SLAB;
#pragma unroll
        for (int ch = 0; ch < 8; ch++) LOAD_CHUNK_W(sbase0, 0, ch);
        CP_COMMIT();
    }

    // ===== wait for previous step's h stores =====
    cudaGridDependencySynchronize();

    // A half of slab 0 (depends on upstream epilogue)
    {
        uint32_t sbase0 = sb + SM_SLAB;
#pragma unroll
        for (int ch = 0; ch < 8; ch++) LOAD_CHUNK_A(sbase0, 0, ch);
        CP_COMMIT();
    }

    uint32_t ah[2][2][4], wh[2][2][4];

#pragma unroll 1
    for (int ks = 0; ks < NSLAB; ks++) {
        CP_WAIT(0);          // current slab's groups complete
        __syncthreads();     // also proves prior-slab reads finished before overwrite

        uint32_t abase = sb + SM_SLAB + (ks & 1) * STAGE_SZ;
        uint32_t nbase = sb + SM_SLAB + ((ks + 1) & 1) * STAGE_SZ;
        int have_next = (ks + 1 < NSLAB);

        LD_FRAGS(0, abase, 0);
#pragma unroll
        for (int kq = 0; kq < 8; kq++) {
            // staggered next-slab loads: 4 chunks per kq for kq = 0..3
            if (kq < 4 && have_next) {
                LOAD_CHUNK_A(nbase, ks + 1, 2 * kq);
                LOAD_CHUNK_A(nbase, ks + 1, 2 * kq + 1);
                LOAD_CHUNK_W(nbase, ks + 1, 2 * kq);
                LOAD_CHUNK_W(nbase, ks + 1, 2 * kq + 1);
                if (kq == 3) CP_COMMIT();
            }
            if (kq < 7) LD_FRAGS((kq + 1) & 1, abase, kq + 1);
            int bb = kq & 1;
#pragma unroll
            for (int mt = 0; mt < 2; mt++) {
#pragma unroll
                for (int j = 0; j < 4; j++) {
                    uint32_t b0 = wh[bb][j >> 1][(j & 1) * 2];
                    uint32_t b1 = wh[bb][j >> 1][(j & 1) * 2 + 1];
                    if (kq & 1) {
                        MMA16816F16(c2[mt][j][0], c2[mt][j][1], c2[mt][j][2], c2[mt][j][3],
                                    ah[bb][mt][0], ah[bb][mt][1], ah[bb][mt][2], ah[bb][mt][3],
                                    b0, b1);
                    } else {
                        MMA16816F16(c[mt][j][0], c[mt][j][1], c[mt][j][2], c[mt][j][3],
                                    ah[bb][mt][0], ah[bb][mt][1], ah[bb][mt][2], ah[bb][mt][3],
                                    b0, b1);
                    }
                }
            }
        }
        __syncthreads();
    }
#undef LOAD_CHUNK_A
#undef LOAD_CHUNK_W
#undef LD_FRAGS

    // mainloop done reading g_hT[src]; let the next step launch and prefetch W
    cudaTriggerProgrammaticLaunchCompletion();

    // ---- epilogue: merge banks, + whx*x + bh, tanh, fp16 store ----
    const float* xs   = (const float*)(smem + SM_XS);
    const float* whxs = (const float*)(smem + SM_WHX);
    const float* bhs  = (const float*)(smem + SM_BH);
    __half* D = g_hT[dst];

#pragma unroll
    for (int mt = 0; mt < 2; mt++) {
#pragma unroll
        for (int half = 0; half < 2; half++) {
            int rloc = wm * 32 + mt * 16 + g + half * 8;
            float xv = xs[rloc];
            size_t rowbase = (size_t)(bt0 + rloc) * HID + n0;
#pragma unroll
            for (int j = 0; j < 4; j++) {
                int nloc = wn * 32 + j * 8 + 2 * tg;
                float v0 = c[mt][j][half * 2 + 0] + c2[mt][j][half * 2 + 0]
                         + whxs[nloc] * xv + bhs[nloc];
                float v1 = c[mt][j][half * 2 + 1] + c2[mt][j][half * 2 + 1]
                         + whxs[nloc + 1] * xv + bhs[nloc + 1];
                __half2 hp = __floats2half2_rn(tanhf(v0), tanhf(v1));
                *(__half2*)(D + rowbase + nloc) = hp;
            }
        }
    }
}

// ================= final projection: one warp per batch row =================
__global__ __launch_bounds__(256) void rnn_proj(
    const float* __restrict__ wph, const float* __restrict__ bp,
    float* __restrict__ out, int src)
{
    int wid = threadIdx.x >> 5, lane = threadIdx.x & 31;
    int b = blockIdx.x * 8 + wid;          // 64 blocks x 8 warps = 512 batches
    const __half2* H = (const __half2*)(g_hT[src] + (size_t)b * HID);

    float acc[NCLS];
#pragma unroll
    for (int c = 0; c < NCLS; c++) acc[c] = 0.f;

#pragma unroll 4
    for (int k2 = lane; k2 < HID / 2; k2 += 32) {
        float2 hv = __half22float2(H[k2]);
#pragma unroll
        for (int c = 0; c < NCLS; c++) {
            const float2 w = *(const float2*)(wph + c * HID + k2 * 2);
            acc[c] = fmaf(w.x, hv.x, fmaf(w.y, hv.y, acc[c]));
        }
    }
#pragma unroll
    for (int c = 0; c < NCLS; c++) {
#pragma unroll
        for (int s = 16; s > 0; s >>= 1)
            acc[c] += __shfl_xor_sync(0xFFFFFFFFu, acc[c], s);
    }
    if (lane < NCLS) out[b * NCLS + lane] = acc[lane] + bp[lane];
}

extern "C" void kernel_launch(void* const* d_in, const int* in_sizes, int n_in,
                              void* d_out, int out_size) {
    const float* x   = (const float*)d_in[0];    // [512, 128]
    const float* whx = (const float*)d_in[1];    // [2048, 1]
    const float* whh = (const float*)d_in[2];    // [2048, 2048]
    const float* bh  = (const float*)d_in[3];    // [2048, 1]
    const float* wph = (const float*)d_in[4];    // [10, 2048]
    const float* bp  = (const float*)d_in[5];    // [10, 1]
    float* out = (float*)d_out;                  // [512, 10]
    (void)in_sizes; (void)n_in; (void)out_size;

    cudaFuncSetAttribute(rnn_step_mma, cudaFuncAttributeMaxDynamicSharedMemorySize, SMEM_TOTAL);

    convert_w<<<(HID * HID + 255) / 256, 256>>>(whh);
    rnn_init<<<(BATCH * HID + 255) / 256, 256>>>(whx, bh, x);

    dim3 grid(HID / BN, BATCH / BM);  // (32, 8) = 256 CTAs -> 2 CTAs/SM

    cudaLaunchConfig_t cfg = {};
    cfg.gridDim = grid;
    cfg.blockDim = dim3(NTHR, 1, 1);
    cfg.dynamicSmemBytes = SMEM_TOTAL;
    cfg.stream = 0;
    cudaLaunchAttribute attrs[1];
    attrs[0].id = cudaLaunchAttributeProgrammaticStreamSerialization;
    attrs[0].val.programmaticStreamSerializationAllowed = 1;
    cfg.attrs = attrs;
    cfg.numAttrs = 1;

    for (int t = 1; t < SEQ; t++) {
        cudaLaunchKernelEx(&cfg, rnn_step_mma, x, whx, bh, t, (t - 1) & 1, t & 1);
    }

    rnn_proj<<<BATCH / 8, 256>>>(wph, bp, out, (SEQ - 1) & 1);  // final h in buf 1
}